// round 10
// baseline (speedup 1.0000x reference)
#include <cuda_runtime.h>
#include <cuda_fp16.h>
#include <cstdint>

#define N_NODES 262144
#define M_EDGES 1048576
#define F_DIM   64
#define H_DIM   128
#define HEADS   3

// Scratch (static __device__ — no allocations allowed)
// Interleaved node-major fp16 tables: entry (n,h) = 256 halves; chunk l (8 halves
// at offset 8l): [gate[4l..4l+3], msg[4l..4l+3]]
__device__ __half g_self_h[(size_t)HEADS * N_NODES * 256];
__device__ __half g_nbr_h [(size_t)HEADS * N_NODES * 256];
__device__ __half g_acc_h[(size_t)HEADS * N_NODES * 128];  // fp16: sum_e attn*leaky(msg hidden)
__device__ float  g_sattn[(size_t)HEADS * N_NODES];        // sum_e attn
__device__ int    g_rowptr[N_NODES + 1];
// Pre-transposed fp16 W1 weights: [z][n][k], z = h*4 + kind
__device__ __half g_wt[12 * 128 * 64];

__device__ __forceinline__ float lk(float x) { return x >= 0.f ? x : 0.01f * x; }

__device__ __forceinline__ void mma_f16(float* c, const uint32_t* a, const uint32_t* b) {
    asm volatile(
        "mma.sync.aligned.m16n8k16.row.col.f32.f16.f16.f32 "
        "{%0,%1,%2,%3},{%4,%5,%6,%7},{%8,%9},{%0,%1,%2,%3};"
        : "+f"(c[0]), "+f"(c[1]), "+f"(c[2]), "+f"(c[3])
        : "r"(a[0]), "r"(a[1]), "r"(a[2]), "r"(a[3]), "r"(b[0]), "r"(b[1]));
}

// ---------------------------------------------------------------------------
// K0: convert+transpose all 12 W1 matrices to fp16 [n][k] layout, once.
// ---------------------------------------------------------------------------
__global__ void prep_weights_kernel(const float* __restrict__ gate_w1,
                                    const float* __restrict__ msg_w1)
{
    const int z = blockIdx.x;
    const int h = z >> 2;
    const int kind = z & 3;
    const float* W;
    if (kind == 0)      W = gate_w1 + (size_t)h*128*128;
    else if (kind == 1) W = msg_w1  + (size_t)h*128*128;
    else if (kind == 2) W = gate_w1 + (size_t)h*128*128 + 64*128;
    else                W = msg_w1  + (size_t)h*128*128 + 64*128;

    __half* dst = g_wt + (size_t)z * 8192;
    for (int i = threadIdx.x; i < 8192; i += 256) {
        const int n = i >> 6;
        const int k = i & 63;
        dst[i] = __float2half(W[(size_t)k * 128 + n]);
    }
}

// ---------------------------------------------------------------------------
// K1: fused node precompute. One block owns a 128-node X tile; loops over 12
// pre-transposed fp16 weight matrices, double-buffered, fp16 m16n8k16 MMA.
// Epilogue writes INTERLEAVED table layout (gate/msg chunks of 4).
// ---------------------------------------------------------------------------
__global__ void __launch_bounds__(256, 2)
node_gemm_kernel(const float* __restrict__ X,
                 const float* __restrict__ gate_b1,
                 const float* __restrict__ msg_b1)
{
    __shared__ __half As[128][72];       // 128 nodes x 64 k
    __shared__ __half Bst[2][128][72];   // double-buffered: 128 out-cols x 64 k

    const int tid  = threadIdx.x;     // 256 threads, 8 warps
    const int wid  = tid >> 5;
    const int lane = tid & 31;
    const int gid  = lane >> 2;       // 0..7
    const int tig  = lane & 3;        // 0..3
    const int warp_m = wid & 3;       // 4 warps over 128 rows
    const int warp_n = wid >> 2;      // 2 warps over 128 cols (64 each)
    const int n0 = blockIdx.x * 128;
    const int cb_w = warp_n * 64;

    // Load X tile 128x64 fp32 -> fp16 smem (once)
    #pragma unroll
    for (int it = 0; it < 8; it++) {
        const int f4 = tid + it * 256;         // 0..2047 float4s
        const int node = f4 >> 4;
        const int c4 = (f4 & 15) * 4;
        float4 v = *(const float4*)(X + (size_t)(n0 + node) * 64 + c4);
        *(__half2*)&As[node][c4]     = __floats2half2_rn(v.x, v.y);
        *(__half2*)&As[node][c4 + 2] = __floats2half2_rn(v.z, v.w);
    }

    // Prefill buffer 0 with z=0 weights
    {
        const __half* src = g_wt;
        #pragma unroll
        for (int it = 0; it < 4; it++) {
            const int idx = tid + it * 256;    // 0..1023
            const int nn = idx >> 3;
            const int k8 = (idx & 7) * 8;
            *(uint4*)&Bst[0][nn][k8] = *(const uint4*)(src + nn * 64 + k8);
        }
    }

    for (int z = 0; z < 12; z++) {
        const int h = z >> 2;
        const int kind = z & 3;
        const float* bias = nullptr;
        if (kind == 0)      bias = gate_b1 + h*128;
        else if (kind == 1) bias = msg_b1  + h*128;
        __half* table = (kind < 2) ? g_self_h : g_nbr_h;
        const bool is_msg = (kind & 1);
        const int buf = z & 1;

        __syncthreads();

        if (z < 11) {
            const __half* src = g_wt + (size_t)(z + 1) * 8192;
            #pragma unroll
            for (int it = 0; it < 4; it++) {
                const int idx = tid + it * 256;
                const int nn = idx >> 3;
                const int k8 = (idx & 7) * 8;
                *(uint4*)&Bst[buf ^ 1][nn][k8] = *(const uint4*)(src + nn * 64 + k8);
            }
        }

        float acc[2][8][4];
        #pragma unroll
        for (int m = 0; m < 2; m++)
            #pragma unroll
            for (int n = 0; n < 8; n++)
                #pragma unroll
                for (int j = 0; j < 4; j++) acc[m][n][j] = 0.f;

        #pragma unroll
        for (int ks = 0; ks < 4; ks++) {
            const int k0 = ks * 16;
            uint32_t a[2][4];
            #pragma unroll
            for (int m = 0; m < 2; m++) {
                const int rb = warp_m * 32 + m * 16;
                a[m][0] = *(const uint32_t*)&As[rb + gid    ][k0 + tig * 2];
                a[m][1] = *(const uint32_t*)&As[rb + gid + 8][k0 + tig * 2];
                a[m][2] = *(const uint32_t*)&As[rb + gid    ][k0 + 8 + tig * 2];
                a[m][3] = *(const uint32_t*)&As[rb + gid + 8][k0 + 8 + tig * 2];
            }
            uint32_t b[8][2];
            #pragma unroll
            for (int n = 0; n < 8; n++) {
                const int col = cb_w + n * 8 + gid;
                b[n][0] = *(const uint32_t*)&Bst[buf][col][k0 + tig * 2];
                b[n][1] = *(const uint32_t*)&Bst[buf][col][k0 + 8 + tig * 2];
            }
            #pragma unroll
            for (int m = 0; m < 2; m++)
                #pragma unroll
                for (int n = 0; n < 8; n++)
                    mma_f16(acc[m][n], a[m], b[n]);
        }

        // Epilogue: add bias, convert fp16, store interleaved node-major:
        // gate col c -> offset (c>>2)*8 + (c&3); msg col c -> (c>>2)*8 + 4 + (c&3)
        #pragma unroll
        for (int m = 0; m < 2; m++) {
            #pragma unroll
            for (int hr = 0; hr < 2; hr++) {
                const int row = n0 + warp_m * 32 + m * 16 + gid + hr * 8;
                __half* dst = table + ((size_t)row * 3 + h) * 256;
                #pragma unroll
                for (int n = 0; n < 8; n++) {
                    const int col = cb_w + n * 8 + 2 * tig;
                    float v0 = acc[m][n][hr * 2 + 0];
                    float v1 = acc[m][n][hr * 2 + 1];
                    if (bias) { v0 += bias[col]; v1 += bias[col + 1]; }
                    const int off = (col >> 2) * 8 + (col & 3) + (is_msg ? 4 : 0);
                    *(__half2*)(dst + off) = __floats2half2_rn(v0, v1);
                }
            }
        }
    }
}

// ---------------------------------------------------------------------------
// CSR row pointers from sorted self_fea_idx
// ---------------------------------------------------------------------------
__global__ void rowptr_kernel(const int* __restrict__ self_idx)
{
    const int e = blockIdx.x * blockDim.x + threadIdx.x;
    if (e >= M_EDGES) return;
    const int s = self_idx[e];
    const int prev = (e == 0) ? -1 : self_idx[e - 1];
    for (int n = prev + 1; n <= s; n++) g_rowptr[n] = e;
    if (e == M_EDGES - 1)
        for (int n = s + 1; n <= N_NODES; n++) g_rowptr[n] = M_EDGES;
}

// ---------------------------------------------------------------------------
// K2: fused softmax + weighted hidden accumulation.
// One warp per (node, head) — max warp count to hide gather latency (R9
// post-mortem: 3-heads-per-warp halved occupancy and lost). Interleaved table:
// ONE LDG.128 per lane per edge.
// ---------------------------------------------------------------------------
__global__ void edge_kernel(const int* __restrict__ nbr_idx,
                            const float* __restrict__ elem_weights,
                            const float* __restrict__ gate_w2,
                            const float* __restrict__ gate_b2)
{
    const int wid = blockIdx.x * 8 + (threadIdx.x >> 5);
    const int lane = threadIdx.x & 31;
    if (wid >= N_NODES * HEADS) return;
    const int n = wid / HEADS;
    const int h = wid - n * HEADS;

    // Self chunk (interleaved): gate[4] then msg[4]
    const uint4 su = *(const uint4*)(g_self_h + ((size_t)n * 3 + h) * 256 + lane * 8);
    const float2 s0 = __half22float2(*(__half2*)&su.x);
    const float2 s1 = __half22float2(*(__half2*)&su.y);
    const float2 s2 = __half22float2(*(__half2*)&su.z);
    const float2 s3 = __half22float2(*(__half2*)&su.w);
    const float sg0 = s0.x, sg1 = s0.y, sg2 = s1.x, sg3 = s1.y;
    const float sm0 = s2.x, sm1 = s2.y, sm2 = s3.x, sm3 = s3.y;
    const float4 w2 = *(const float4*)(gate_w2 + h * 128 + lane * 4);
    const float b2 = gate_b2[h];

    const int e0 = g_rowptr[n];
    const int e1 = g_rowptr[n + 1];

    float nx = 0.f, ny = 0.f, nz = 0.f, nw = 0.f;
    float denom = 0.f;

    for (int e = e0; e < e1; e++) {
        const int j = __ldg(&nbr_idx[e]);
        const float w = __ldg(&elem_weights[j]);
        const uint4 u = *(const uint4*)(g_nbr_h + ((size_t)j * 3 + h) * 256 + lane * 8);
        const float2 a0 = __half22float2(*(__half2*)&u.x);
        const float2 a1 = __half22float2(*(__half2*)&u.y);
        const float2 a2 = __half22float2(*(__half2*)&u.z);
        const float2 a3 = __half22float2(*(__half2*)&u.w);

        float p = lk(sg0 + a0.x) * w2.x + lk(sg1 + a0.y) * w2.y
                + lk(sg2 + a1.x) * w2.z + lk(sg3 + a1.y) * w2.w;
        p += __shfl_xor_sync(0xffffffffu, p, 16);
        p += __shfl_xor_sync(0xffffffffu, p, 8);
        p += __shfl_xor_sync(0xffffffffu, p, 4);
        p += __shfl_xor_sync(0xffffffffu, p, 2);
        p += __shfl_xor_sync(0xffffffffu, p, 1);
        const float ev = w * __expf(p + b2);
        denom += ev;

        nx += ev * lk(sm0 + a2.x);
        ny += ev * lk(sm1 + a2.y);
        nz += ev * lk(sm2 + a3.x);
        nw += ev * lk(sm3 + a3.y);
    }

    const float inv = 1.f / (denom + 1e-10f);
    __half2 h0 = __floats2half2_rn(nx * inv, ny * inv);
    __half2 h1 = __floats2half2_rn(nz * inv, nw * inv);
    uint2 uo;
    uo.x = *(uint32_t*)&h0;
    uo.y = *(uint32_t*)&h1;
    *(uint2*)(g_acc_h + ((size_t)h * N_NODES + n) * 128 + lane * 4) = uo;
    if (lane == 0) g_sattn[(size_t)h * N_NODES + n] = denom * inv;
}

// ---------------------------------------------------------------------------
// K3: out[n][f] = x[n][f] + (1/3) * sum_h ( acc[h][n] @ msg_w2[h] + sattn[h][n]*msg_b2[h][f] )
// GEMM via fp16 mma.m16n8k16: C[N x 64] = A[N x 384] @ W[384 x 64]
// ---------------------------------------------------------------------------
__global__ void __launch_bounds__(256, 2)
out_gemm_kernel(const float* __restrict__ msg_w2,
                const float* __restrict__ msg_b2,
                const float* __restrict__ X,
                float* __restrict__ out)
{
    __shared__ __half As[128][88];   // 128 nodes x 64 k (fp16)
    __shared__ __half Bst[64][88];   // 64 cols x 64 k (transposed, fp16)

    const int tid  = threadIdx.x;    // 256 threads, 8 warps
    const int wid  = tid >> 5;
    const int lane = tid & 31;
    const int gid  = lane >> 2;      // 0..7
    const int tig  = lane & 3;       // 0..3
    const int warp_m = wid & 3;      // 4 warps over 128 rows (32 each)
    const int warp_n = wid >> 2;     // 2 warps over 64 cols (32 each)
    const int n0 = blockIdx.x * 128;
    const int cb = warp_n * 32;

    float acc[2][4][4];
    #pragma unroll
    for (int mt = 0; mt < 2; mt++)
        #pragma unroll
        for (int nt = 0; nt < 4; nt++)
            #pragma unroll
            for (int jj = 0; jj < 4; jj++) acc[mt][nt][jj] = 0.f;

    #pragma unroll
    for (int kc = 0; kc < 6; kc++) {
        const int h = kc >> 1;
        const __half* asrc = g_acc_h + ((size_t)h * N_NODES + n0) * 128 + (kc & 1) * 64;
        #pragma unroll
        for (int it = 0; it < 4; it++) {
            const int f4 = tid + it * 256;
            const int node = f4 >> 3;
            const int c8 = (f4 & 7) * 8;
            *(uint4*)&As[node][c8] = *(const uint4*)(asrc + (size_t)node * 128 + c8);
        }
        const float* bsrc = msg_w2 + ((size_t)h * 128 + (kc & 1) * 64) * 64;
        #pragma unroll
        for (int i = 0; i < 16; i++) {
            const int idx = i * 256 + tid;
            const int nn = idx & 63;
            const int kk = idx >> 6;
            Bst[nn][kk] = __float2half(bsrc[(size_t)kk * 64 + nn]);
        }
        __syncthreads();

        #pragma unroll
        for (int ks = 0; ks < 4; ks++) {
            const int k0 = ks * 16;
            uint32_t a[2][4];
            #pragma unroll
            for (int mt = 0; mt < 2; mt++) {
                const int rb = warp_m * 32 + mt * 16;
                a[mt][0] = *(const uint32_t*)&As[rb + gid    ][k0 + tig * 2];
                a[mt][1] = *(const uint32_t*)&As[rb + gid + 8][k0 + tig * 2];
                a[mt][2] = *(const uint32_t*)&As[rb + gid    ][k0 + 8 + tig * 2];
                a[mt][3] = *(const uint32_t*)&As[rb + gid + 8][k0 + 8 + tig * 2];
            }
            uint32_t b[4][2];
            #pragma unroll
            for (int nt = 0; nt < 4; nt++) {
                const int col = cb + nt * 8 + gid;
                b[nt][0] = *(const uint32_t*)&Bst[col][k0 + tig * 2];
                b[nt][1] = *(const uint32_t*)&Bst[col][k0 + 8 + tig * 2];
            }
            #pragma unroll
            for (int mt = 0; mt < 2; mt++)
                #pragma unroll
                for (int nt = 0; nt < 4; nt++)
                    mma_f16(acc[mt][nt], a[mt], b[nt]);
        }
        __syncthreads();
    }

    // Epilogue
    const float inv3 = 1.f / 3.f;
    #pragma unroll
    for (int mt = 0; mt < 2; mt++) {
        #pragma unroll
        for (int hf = 0; hf < 2; hf++) {
            const int r = n0 + warp_m * 32 + mt * 16 + gid + hf * 8;
            const float s0 = g_sattn[r];
            const float s1 = g_sattn[(size_t)N_NODES + r];
            const float s2 = g_sattn[(size_t)2 * N_NODES + r];
            #pragma unroll
            for (int nt = 0; nt < 4; nt++) {
                const int c = cb + nt * 8 + tig * 2;
                const float bt0 = s0 * msg_b2[c]     + s1 * msg_b2[64 + c]     + s2 * msg_b2[128 + c];
                const float bt1 = s0 * msg_b2[c + 1] + s1 * msg_b2[64 + c + 1] + s2 * msg_b2[128 + c + 1];
                const float2 xv = *(const float2*)(X + (size_t)r * 64 + c);
                float2 o;
                o.x = inv3 * (acc[mt][nt][hf * 2 + 0] + bt0) + xv.x;
                o.y = inv3 * (acc[mt][nt][hf * 2 + 1] + bt1) + xv.y;
                *(float2*)(out + (size_t)r * 64 + c) = o;
            }
        }
    }
}

// ---------------------------------------------------------------------------
extern "C" void kernel_launch(void* const* d_in, const int* in_sizes, int n_in,
                              void* d_out, int out_size)
{
    const float* elem_weights = (const float*)d_in[0];
    const float* x            = (const float*)d_in[1];
    const int*   self_idx     = (const int*)  d_in[2];
    const int*   nbr_idx      = (const int*)  d_in[3];
    const float* gate_w1      = (const float*)d_in[4];
    const float* gate_b1      = (const float*)d_in[5];
    const float* gate_w2      = (const float*)d_in[6];
    const float* gate_b2      = (const float*)d_in[7];
    const float* msg_w1       = (const float*)d_in[8];
    const float* msg_b1       = (const float*)d_in[9];
    const float* msg_w2       = (const float*)d_in[10];
    const float* msg_b2       = (const float*)d_in[11];
    float* out = (float*)d_out;

    prep_weights_kernel<<<12, 256>>>(gate_w1, msg_w1);
    node_gemm_kernel<<<N_NODES / 128, 256>>>(x, gate_b1, msg_b1);
    rowptr_kernel<<<M_EDGES / 256, 256>>>(self_idx);
    edge_kernel<<<(N_NODES * HEADS) / 8, 256>>>(nbr_idx, elem_weights, gate_w2, gate_b2);
    out_gemm_kernel<<<N_NODES / 128, 256>>>(msg_w2, msg_b2, x, out);
}

// round 11
// speedup vs baseline: 1.0985x; 1.0985x over previous
#include <cuda_runtime.h>
#include <cuda_fp16.h>
#include <cstdint>

#define N_NODES 262144
#define M_EDGES 1048576
#define F_DIM   64
#define H_DIM   128
#define HEADS   3

// Scratch (static __device__ — no allocations allowed)
// Interleaved node-major fp16 tables: entry (n,h) = 256 halves; chunk l (8 halves
// at offset 8l): [gate[4l..4l+3], msg[4l..4l+3]]
__device__ __half g_self_h[(size_t)HEADS * N_NODES * 256];
__device__ __half g_nbr_h [(size_t)HEADS * N_NODES * 256];
__device__ __half g_acc_h[(size_t)HEADS * N_NODES * 128];  // fp16: sum_e attn*leaky(msg hidden)
__device__ float  g_sattn[(size_t)HEADS * N_NODES];        // sum_e attn
__device__ int    g_rowptr[N_NODES + 1];
// Pre-transposed fp16 W1 weights: [z][n][k], z = h*4 + kind
__device__ __half g_wt[12 * 128 * 64];

__device__ __forceinline__ float lk(float x) { return x >= 0.f ? x : 0.01f * x; }

__device__ __forceinline__ void mma_f16(float* c, const uint32_t* a, const uint32_t* b) {
    asm volatile(
        "mma.sync.aligned.m16n8k16.row.col.f32.f16.f16.f32 "
        "{%0,%1,%2,%3},{%4,%5,%6,%7},{%8,%9},{%0,%1,%2,%3};"
        : "+f"(c[0]), "+f"(c[1]), "+f"(c[2]), "+f"(c[3])
        : "r"(a[0]), "r"(a[1]), "r"(a[2]), "r"(a[3]), "r"(b[0]), "r"(b[1]));
}

// ---------------------------------------------------------------------------
// K0: convert+transpose all 12 W1 matrices to fp16 [n][k] layout, once.
// ---------------------------------------------------------------------------
__global__ void prep_weights_kernel(const float* __restrict__ gate_w1,
                                    const float* __restrict__ msg_w1)
{
    const int z = blockIdx.x;
    const int h = z >> 2;
    const int kind = z & 3;
    const float* W;
    if (kind == 0)      W = gate_w1 + (size_t)h*128*128;
    else if (kind == 1) W = msg_w1  + (size_t)h*128*128;
    else if (kind == 2) W = gate_w1 + (size_t)h*128*128 + 64*128;
    else                W = msg_w1  + (size_t)h*128*128 + 64*128;

    __half* dst = g_wt + (size_t)z * 8192;
    for (int i = threadIdx.x; i < 8192; i += 256) {
        const int n = i >> 6;
        const int k = i & 63;
        dst[i] = __float2half(W[(size_t)k * 128 + n]);
    }
}

// ---------------------------------------------------------------------------
// K1: fused node precompute. One block owns a 128-node X tile; loops over 12
// pre-transposed fp16 weight matrices, double-buffered, fp16 m16n8k16 MMA.
// Epilogue writes INTERLEAVED table layout (gate/msg chunks of 4).
// ---------------------------------------------------------------------------
__global__ void __launch_bounds__(256, 2)
node_gemm_kernel(const float* __restrict__ X,
                 const float* __restrict__ gate_b1,
                 const float* __restrict__ msg_b1)
{
    __shared__ __half As[128][72];       // 128 nodes x 64 k
    __shared__ __half Bst[2][128][72];   // double-buffered: 128 out-cols x 64 k

    const int tid  = threadIdx.x;     // 256 threads, 8 warps
    const int wid  = tid >> 5;
    const int lane = tid & 31;
    const int gid  = lane >> 2;       // 0..7
    const int tig  = lane & 3;        // 0..3
    const int warp_m = wid & 3;       // 4 warps over 128 rows
    const int warp_n = wid >> 2;      // 2 warps over 128 cols (64 each)
    const int n0 = blockIdx.x * 128;
    const int cb_w = warp_n * 64;

    // Load X tile 128x64 fp32 -> fp16 smem (once)
    #pragma unroll
    for (int it = 0; it < 8; it++) {
        const int f4 = tid + it * 256;         // 0..2047 float4s
        const int node = f4 >> 4;
        const int c4 = (f4 & 15) * 4;
        float4 v = *(const float4*)(X + (size_t)(n0 + node) * 64 + c4);
        *(__half2*)&As[node][c4]     = __floats2half2_rn(v.x, v.y);
        *(__half2*)&As[node][c4 + 2] = __floats2half2_rn(v.z, v.w);
    }

    // Prefill buffer 0 with z=0 weights
    {
        const __half* src = g_wt;
        #pragma unroll
        for (int it = 0; it < 4; it++) {
            const int idx = tid + it * 256;    // 0..1023
            const int nn = idx >> 3;
            const int k8 = (idx & 7) * 8;
            *(uint4*)&Bst[0][nn][k8] = *(const uint4*)(src + nn * 64 + k8);
        }
    }

    for (int z = 0; z < 12; z++) {
        const int h = z >> 2;
        const int kind = z & 3;
        const float* bias = nullptr;
        if (kind == 0)      bias = gate_b1 + h*128;
        else if (kind == 1) bias = msg_b1  + h*128;
        __half* table = (kind < 2) ? g_self_h : g_nbr_h;
        const bool is_msg = (kind & 1);
        const int buf = z & 1;

        __syncthreads();

        if (z < 11) {
            const __half* src = g_wt + (size_t)(z + 1) * 8192;
            #pragma unroll
            for (int it = 0; it < 4; it++) {
                const int idx = tid + it * 256;
                const int nn = idx >> 3;
                const int k8 = (idx & 7) * 8;
                *(uint4*)&Bst[buf ^ 1][nn][k8] = *(const uint4*)(src + nn * 64 + k8);
            }
        }

        float acc[2][8][4];
        #pragma unroll
        for (int m = 0; m < 2; m++)
            #pragma unroll
            for (int n = 0; n < 8; n++)
                #pragma unroll
                for (int j = 0; j < 4; j++) acc[m][n][j] = 0.f;

        #pragma unroll
        for (int ks = 0; ks < 4; ks++) {
            const int k0 = ks * 16;
            uint32_t a[2][4];
            #pragma unroll
            for (int m = 0; m < 2; m++) {
                const int rb = warp_m * 32 + m * 16;
                a[m][0] = *(const uint32_t*)&As[rb + gid    ][k0 + tig * 2];
                a[m][1] = *(const uint32_t*)&As[rb + gid + 8][k0 + tig * 2];
                a[m][2] = *(const uint32_t*)&As[rb + gid    ][k0 + 8 + tig * 2];
                a[m][3] = *(const uint32_t*)&As[rb + gid + 8][k0 + 8 + tig * 2];
            }
            uint32_t b[8][2];
            #pragma unroll
            for (int n = 0; n < 8; n++) {
                const int col = cb_w + n * 8 + gid;
                b[n][0] = *(const uint32_t*)&Bst[buf][col][k0 + tig * 2];
                b[n][1] = *(const uint32_t*)&Bst[buf][col][k0 + 8 + tig * 2];
            }
            #pragma unroll
            for (int m = 0; m < 2; m++)
                #pragma unroll
                for (int n = 0; n < 8; n++)
                    mma_f16(acc[m][n], a[m], b[n]);
        }

        // Epilogue: add bias, convert fp16, store interleaved node-major:
        // gate col c -> offset (c>>2)*8 + (c&3); msg col c -> (c>>2)*8 + 4 + (c&3)
        #pragma unroll
        for (int m = 0; m < 2; m++) {
            #pragma unroll
            for (int hr = 0; hr < 2; hr++) {
                const int row = n0 + warp_m * 32 + m * 16 + gid + hr * 8;
                __half* dst = table + ((size_t)row * 3 + h) * 256;
                #pragma unroll
                for (int n = 0; n < 8; n++) {
                    const int col = cb_w + n * 8 + 2 * tig;
                    float v0 = acc[m][n][hr * 2 + 0];
                    float v1 = acc[m][n][hr * 2 + 1];
                    if (bias) { v0 += bias[col]; v1 += bias[col + 1]; }
                    const int off = (col >> 2) * 8 + (col & 3) + (is_msg ? 4 : 0);
                    *(__half2*)(dst + off) = __floats2half2_rn(v0, v1);
                }
            }
        }
    }
}

// ---------------------------------------------------------------------------
// CSR row pointers from sorted self_fea_idx
// ---------------------------------------------------------------------------
__global__ void rowptr_kernel(const int* __restrict__ self_idx)
{
    const int e = blockIdx.x * blockDim.x + threadIdx.x;
    if (e >= M_EDGES) return;
    const int s = self_idx[e];
    const int prev = (e == 0) ? -1 : self_idx[e - 1];
    for (int n = prev + 1; n <= s; n++) g_rowptr[n] = e;
    if (e == M_EDGES - 1)
        for (int n = s + 1; n <= N_NODES; n++) g_rowptr[n] = M_EDGES;
}

// ---------------------------------------------------------------------------
// K2: fused softmax + weighted hidden accumulation.
// One warp per NODE, all 3 heads in-flight (R9 variant — measured fastest:
// MLP=3 independent 512B gathers per edge from one contiguous 1536B block,
// idx/weight loaded once). 128-thread blocks + launch_bounds(128,6) to lift
// occupancy from R9's 2-CTA/25% to ~6-CTA/37.5%.
// ---------------------------------------------------------------------------
__global__ void __launch_bounds__(128, 6)
edge_kernel(const int* __restrict__ nbr_idx,
            const float* __restrict__ elem_weights,
            const float* __restrict__ gate_w2,
            const float* __restrict__ gate_b2)
{
    const int n = blockIdx.x * 4 + (threadIdx.x >> 5);
    const int lane = threadIdx.x & 31;
    if (n >= N_NODES) return;

    // Self chunks + w2 + b2 per head
    float sg[3][4], sm[3][4], w2v[3][4], b2[3];
    #pragma unroll
    for (int h = 0; h < 3; h++) {
        const uint4 u = *(const uint4*)(g_self_h + ((size_t)n * 3 + h) * 256 + lane * 8);
        const float2 a0 = __half22float2(*(__half2*)&u.x);
        const float2 a1 = __half22float2(*(__half2*)&u.y);
        const float2 a2 = __half22float2(*(__half2*)&u.z);
        const float2 a3 = __half22float2(*(__half2*)&u.w);
        sg[h][0] = a0.x; sg[h][1] = a0.y; sg[h][2] = a1.x; sg[h][3] = a1.y;
        sm[h][0] = a2.x; sm[h][1] = a2.y; sm[h][2] = a3.x; sm[h][3] = a3.y;
        const float4 wv = *(const float4*)(gate_w2 + h * 128 + lane * 4);
        w2v[h][0] = wv.x; w2v[h][1] = wv.y; w2v[h][2] = wv.z; w2v[h][3] = wv.w;
        b2[h] = gate_b2[h];
    }

    const int e0 = g_rowptr[n];
    const int e1 = g_rowptr[n + 1];

    float acc[3][4];
    float denom[3] = {0.f, 0.f, 0.f};
    #pragma unroll
    for (int h = 0; h < 3; h++)
        #pragma unroll
        for (int d = 0; d < 4; d++) acc[h][d] = 0.f;

    for (int e = e0; e < e1; e++) {
        const int j = __ldg(&nbr_idx[e]);
        const float w = __ldg(&elem_weights[j]);

        uint4 u[3];
        #pragma unroll
        for (int h = 0; h < 3; h++)
            u[h] = *(const uint4*)(g_nbr_h + ((size_t)j * 3 + h) * 256 + lane * 8);

        float p[3], nm[3][4];
        #pragma unroll
        for (int h = 0; h < 3; h++) {
            const float2 a0 = __half22float2(*(__half2*)&u[h].x);
            const float2 a1 = __half22float2(*(__half2*)&u[h].y);
            const float2 a2 = __half22float2(*(__half2*)&u[h].z);
            const float2 a3 = __half22float2(*(__half2*)&u[h].w);
            p[h] = lk(sg[h][0] + a0.x) * w2v[h][0]
                 + lk(sg[h][1] + a0.y) * w2v[h][1]
                 + lk(sg[h][2] + a1.x) * w2v[h][2]
                 + lk(sg[h][3] + a1.y) * w2v[h][3];
            nm[h][0] = a2.x; nm[h][1] = a2.y; nm[h][2] = a3.x; nm[h][3] = a3.y;
        }
        // 3 interleaved butterflies
        #pragma unroll
        for (int s = 16; s >= 1; s >>= 1) {
            p[0] += __shfl_xor_sync(0xffffffffu, p[0], s);
            p[1] += __shfl_xor_sync(0xffffffffu, p[1], s);
            p[2] += __shfl_xor_sync(0xffffffffu, p[2], s);
        }
        #pragma unroll
        for (int h = 0; h < 3; h++) {
            const float ev = w * __expf(p[h] + b2[h]);
            denom[h] += ev;
            acc[h][0] += ev * lk(sm[h][0] + nm[h][0]);
            acc[h][1] += ev * lk(sm[h][1] + nm[h][1]);
            acc[h][2] += ev * lk(sm[h][2] + nm[h][2]);
            acc[h][3] += ev * lk(sm[h][3] + nm[h][3]);
        }
    }

    #pragma unroll
    for (int h = 0; h < 3; h++) {
        const float inv = 1.f / (denom[h] + 1e-10f);
        __half2 h0 = __floats2half2_rn(acc[h][0] * inv, acc[h][1] * inv);
        __half2 h1 = __floats2half2_rn(acc[h][2] * inv, acc[h][3] * inv);
        uint2 uo;
        uo.x = *(uint32_t*)&h0;
        uo.y = *(uint32_t*)&h1;
        *(uint2*)(g_acc_h + ((size_t)h * N_NODES + n) * 128 + lane * 4) = uo;
        if (lane == 0) g_sattn[(size_t)h * N_NODES + n] = denom[h] * inv;
    }
}

// ---------------------------------------------------------------------------
// K3: out[n][f] = x[n][f] + (1/3) * sum_h ( acc[h][n] @ msg_w2[h] + sattn[h][n]*msg_b2[h][f] )
// GEMM via fp16 mma.m16n8k16: C[N x 64] = A[N x 384] @ W[384 x 64]
// ---------------------------------------------------------------------------
__global__ void __launch_bounds__(256, 2)
out_gemm_kernel(const float* __restrict__ msg_w2,
                const float* __restrict__ msg_b2,
                const float* __restrict__ X,
                float* __restrict__ out)
{
    __shared__ __half As[128][88];   // 128 nodes x 64 k (fp16)
    __shared__ __half Bst[64][88];   // 64 cols x 64 k (transposed, fp16)

    const int tid  = threadIdx.x;    // 256 threads, 8 warps
    const int wid  = tid >> 5;
    const int lane = tid & 31;
    const int gid  = lane >> 2;      // 0..7
    const int tig  = lane & 3;       // 0..3
    const int warp_m = wid & 3;      // 4 warps over 128 rows (32 each)
    const int warp_n = wid >> 2;     // 2 warps over 64 cols (32 each)
    const int n0 = blockIdx.x * 128;
    const int cb = warp_n * 32;

    float acc[2][4][4];
    #pragma unroll
    for (int mt = 0; mt < 2; mt++)
        #pragma unroll
        for (int nt = 0; nt < 4; nt++)
            #pragma unroll
            for (int jj = 0; jj < 4; jj++) acc[mt][nt][jj] = 0.f;

    #pragma unroll
    for (int kc = 0; kc < 6; kc++) {
        const int h = kc >> 1;
        const __half* asrc = g_acc_h + ((size_t)h * N_NODES + n0) * 128 + (kc & 1) * 64;
        #pragma unroll
        for (int it = 0; it < 4; it++) {
            const int f4 = tid + it * 256;
            const int node = f4 >> 3;
            const int c8 = (f4 & 7) * 8;
            *(uint4*)&As[node][c8] = *(const uint4*)(asrc + (size_t)node * 128 + c8);
        }
        const float* bsrc = msg_w2 + ((size_t)h * 128 + (kc & 1) * 64) * 64;
        #pragma unroll
        for (int i = 0; i < 16; i++) {
            const int idx = i * 256 + tid;
            const int nn = idx & 63;
            const int kk = idx >> 6;
            Bst[nn][kk] = __float2half(bsrc[(size_t)kk * 64 + nn]);
        }
        __syncthreads();

        #pragma unroll
        for (int ks = 0; ks < 4; ks++) {
            const int k0 = ks * 16;
            uint32_t a[2][4];
            #pragma unroll
            for (int mt = 0; mt < 2; mt++) {
                const int rb = warp_m * 32 + mt * 16;
                a[mt][0] = *(const uint32_t*)&As[rb + gid    ][k0 + tig * 2];
                a[mt][1] = *(const uint32_t*)&As[rb + gid + 8][k0 + tig * 2];
                a[mt][2] = *(const uint32_t*)&As[rb + gid    ][k0 + 8 + tig * 2];
                a[mt][3] = *(const uint32_t*)&As[rb + gid + 8][k0 + 8 + tig * 2];
            }
            uint32_t b[4][2];
            #pragma unroll
            for (int nt = 0; nt < 4; nt++) {
                const int col = cb + nt * 8 + gid;
                b[nt][0] = *(const uint32_t*)&Bst[col][k0 + tig * 2];
                b[nt][1] = *(const uint32_t*)&Bst[col][k0 + 8 + tig * 2];
            }
            #pragma unroll
            for (int mt = 0; mt < 2; mt++)
                #pragma unroll
                for (int nt = 0; nt < 4; nt++)
                    mma_f16(acc[mt][nt], a[mt], b[nt]);
        }
        __syncthreads();
    }

    // Epilogue
    const float inv3 = 1.f / 3.f;
    #pragma unroll
    for (int mt = 0; mt < 2; mt++) {
        #pragma unroll
        for (int hf = 0; hf < 2; hf++) {
            const int r = n0 + warp_m * 32 + mt * 16 + gid + hf * 8;
            const float s0 = g_sattn[r];
            const float s1 = g_sattn[(size_t)N_NODES + r];
            const float s2 = g_sattn[(size_t)2 * N_NODES + r];
            #pragma unroll
            for (int nt = 0; nt < 4; nt++) {
                const int c = cb + nt * 8 + tig * 2;
                const float bt0 = s0 * msg_b2[c]     + s1 * msg_b2[64 + c]     + s2 * msg_b2[128 + c];
                const float bt1 = s0 * msg_b2[c + 1] + s1 * msg_b2[64 + c + 1] + s2 * msg_b2[128 + c + 1];
                const float2 xv = *(const float2*)(X + (size_t)r * 64 + c);
                float2 o;
                o.x = inv3 * (acc[mt][nt][hf * 2 + 0] + bt0) + xv.x;
                o.y = inv3 * (acc[mt][nt][hf * 2 + 1] + bt1) + xv.y;
                *(float2*)(out + (size_t)r * 64 + c) = o;
            }
        }
    }
}

// ---------------------------------------------------------------------------
extern "C" void kernel_launch(void* const* d_in, const int* in_sizes, int n_in,
                              void* d_out, int out_size)
{
    const float* elem_weights = (const float*)d_in[0];
    const float* x            = (const float*)d_in[1];
    const int*   self_idx     = (const int*)  d_in[2];
    const int*   nbr_idx      = (const int*)  d_in[3];
    const float* gate_w1      = (const float*)d_in[4];
    const float* gate_b1      = (const float*)d_in[5];
    const float* gate_w2      = (const float*)d_in[6];
    const float* gate_b2      = (const float*)d_in[7];
    const float* msg_w1       = (const float*)d_in[8];
    const float* msg_b1       = (const float*)d_in[9];
    const float* msg_w2       = (const float*)d_in[10];
    const float* msg_b2       = (const float*)d_in[11];
    float* out = (float*)d_out;

    prep_weights_kernel<<<12, 256>>>(gate_w1, msg_w1);
    node_gemm_kernel<<<N_NODES / 128, 256>>>(x, gate_b1, msg_b1);
    rowptr_kernel<<<M_EDGES / 256, 256>>>(self_idx);
    edge_kernel<<<N_NODES / 4, 128>>>(nbr_idx, elem_weights, gate_w2, gate_b2);
    out_gemm_kernel<<<N_NODES / 128, 256>>>(msg_w2, msg_b2, x, out);
}

// round 12
// speedup vs baseline: 1.1272x; 1.0261x over previous
#include <cuda_runtime.h>
#include <cuda_fp16.h>
#include <cstdint>

#define N_NODES 262144
#define M_EDGES 1048576
#define F_DIM   64
#define H_DIM   128
#define HEADS   3

// Scratch (static __device__ — no allocations allowed)
// Interleaved node-major fp16 tables: entry (n,h) = 256 halves; chunk l (8 halves
// at offset 8l): [gate[4l..4l+3], msg[4l..4l+3]]
__device__ __half g_self_h[(size_t)HEADS * N_NODES * 256];
__device__ __half g_nbr_h [(size_t)HEADS * N_NODES * 256];
__device__ __half g_acc_h[(size_t)HEADS * N_NODES * 128];  // fp16: sum_e attn*leaky(msg hidden)
__device__ float  g_sattn[(size_t)HEADS * N_NODES];        // sum_e attn
__device__ int    g_rowptr[N_NODES + 1];
// Pre-transposed fp16 W1 weights: [z][n][k], z = h*4 + kind
__device__ __half g_wt[12 * 128 * 64];

__device__ __forceinline__ float lk(float x) { return x >= 0.f ? x : 0.01f * x; }

__device__ __forceinline__ void mma_f16(float* c, const uint32_t* a, const uint32_t* b) {
    asm volatile(
        "mma.sync.aligned.m16n8k16.row.col.f32.f16.f16.f32 "
        "{%0,%1,%2,%3},{%4,%5,%6,%7},{%8,%9},{%0,%1,%2,%3};"
        : "+f"(c[0]), "+f"(c[1]), "+f"(c[2]), "+f"(c[3])
        : "r"(a[0]), "r"(a[1]), "r"(a[2]), "r"(a[3]), "r"(b[0]), "r"(b[1]));
}

// ---------------------------------------------------------------------------
// K0: convert+transpose all 12 W1 matrices to fp16 [n][k] layout, once.
// ---------------------------------------------------------------------------
__global__ void prep_weights_kernel(const float* __restrict__ gate_w1,
                                    const float* __restrict__ msg_w1)
{
    const int z = blockIdx.x;
    const int h = z >> 2;
    const int kind = z & 3;
    const float* W;
    if (kind == 0)      W = gate_w1 + (size_t)h*128*128;
    else if (kind == 1) W = msg_w1  + (size_t)h*128*128;
    else if (kind == 2) W = gate_w1 + (size_t)h*128*128 + 64*128;
    else                W = msg_w1  + (size_t)h*128*128 + 64*128;

    __half* dst = g_wt + (size_t)z * 8192;
    for (int i = threadIdx.x; i < 8192; i += 256) {
        const int n = i >> 6;
        const int k = i & 63;
        dst[i] = __float2half(W[(size_t)k * 128 + n]);
    }
}

// ---------------------------------------------------------------------------
// K1: fused node precompute. One block owns a 128-node X tile; loops over 12
// pre-transposed fp16 weight matrices, double-buffered, fp16 m16n8k16 MMA.
// Epilogue writes INTERLEAVED table layout (gate/msg chunks of 4).
// ---------------------------------------------------------------------------
__global__ void __launch_bounds__(256, 2)
node_gemm_kernel(const float* __restrict__ X,
                 const float* __restrict__ gate_b1,
                 const float* __restrict__ msg_b1)
{
    __shared__ __half As[128][72];       // 128 nodes x 64 k
    __shared__ __half Bst[2][128][72];   // double-buffered: 128 out-cols x 64 k

    const int tid  = threadIdx.x;     // 256 threads, 8 warps
    const int wid  = tid >> 5;
    const int lane = tid & 31;
    const int gid  = lane >> 2;       // 0..7
    const int tig  = lane & 3;        // 0..3
    const int warp_m = wid & 3;       // 4 warps over 128 rows
    const int warp_n = wid >> 2;      // 2 warps over 128 cols (64 each)
    const int n0 = blockIdx.x * 128;
    const int cb_w = warp_n * 64;

    // Load X tile 128x64 fp32 -> fp16 smem (once)
    #pragma unroll
    for (int it = 0; it < 8; it++) {
        const int f4 = tid + it * 256;         // 0..2047 float4s
        const int node = f4 >> 4;
        const int c4 = (f4 & 15) * 4;
        float4 v = *(const float4*)(X + (size_t)(n0 + node) * 64 + c4);
        *(__half2*)&As[node][c4]     = __floats2half2_rn(v.x, v.y);
        *(__half2*)&As[node][c4 + 2] = __floats2half2_rn(v.z, v.w);
    }

    // Prefill buffer 0 with z=0 weights
    {
        const __half* src = g_wt;
        #pragma unroll
        for (int it = 0; it < 4; it++) {
            const int idx = tid + it * 256;    // 0..1023
            const int nn = idx >> 3;
            const int k8 = (idx & 7) * 8;
            *(uint4*)&Bst[0][nn][k8] = *(const uint4*)(src + nn * 64 + k8);
        }
    }

    for (int z = 0; z < 12; z++) {
        const int h = z >> 2;
        const int kind = z & 3;
        const float* bias = nullptr;
        if (kind == 0)      bias = gate_b1 + h*128;
        else if (kind == 1) bias = msg_b1  + h*128;
        __half* table = (kind < 2) ? g_self_h : g_nbr_h;
        const bool is_msg = (kind & 1);
        const int buf = z & 1;

        __syncthreads();

        if (z < 11) {
            const __half* src = g_wt + (size_t)(z + 1) * 8192;
            #pragma unroll
            for (int it = 0; it < 4; it++) {
                const int idx = tid + it * 256;
                const int nn = idx >> 3;
                const int k8 = (idx & 7) * 8;
                *(uint4*)&Bst[buf ^ 1][nn][k8] = *(const uint4*)(src + nn * 64 + k8);
            }
        }

        float acc[2][8][4];
        #pragma unroll
        for (int m = 0; m < 2; m++)
            #pragma unroll
            for (int n = 0; n < 8; n++)
                #pragma unroll
                for (int j = 0; j < 4; j++) acc[m][n][j] = 0.f;

        #pragma unroll
        for (int ks = 0; ks < 4; ks++) {
            const int k0 = ks * 16;
            uint32_t a[2][4];
            #pragma unroll
            for (int m = 0; m < 2; m++) {
                const int rb = warp_m * 32 + m * 16;
                a[m][0] = *(const uint32_t*)&As[rb + gid    ][k0 + tig * 2];
                a[m][1] = *(const uint32_t*)&As[rb + gid + 8][k0 + tig * 2];
                a[m][2] = *(const uint32_t*)&As[rb + gid    ][k0 + 8 + tig * 2];
                a[m][3] = *(const uint32_t*)&As[rb + gid + 8][k0 + 8 + tig * 2];
            }
            uint32_t b[8][2];
            #pragma unroll
            for (int n = 0; n < 8; n++) {
                const int col = cb_w + n * 8 + gid;
                b[n][0] = *(const uint32_t*)&Bst[buf][col][k0 + tig * 2];
                b[n][1] = *(const uint32_t*)&Bst[buf][col][k0 + 8 + tig * 2];
            }
            #pragma unroll
            for (int m = 0; m < 2; m++)
                #pragma unroll
                for (int n = 0; n < 8; n++)
                    mma_f16(acc[m][n], a[m], b[n]);
        }

        // Epilogue: add bias, convert fp16, store interleaved node-major:
        // gate col c -> offset (c>>2)*8 + (c&3); msg col c -> (c>>2)*8 + 4 + (c&3)
        #pragma unroll
        for (int m = 0; m < 2; m++) {
            #pragma unroll
            for (int hr = 0; hr < 2; hr++) {
                const int row = n0 + warp_m * 32 + m * 16 + gid + hr * 8;
                __half* dst = table + ((size_t)row * 3 + h) * 256;
                #pragma unroll
                for (int n = 0; n < 8; n++) {
                    const int col = cb_w + n * 8 + 2 * tig;
                    float v0 = acc[m][n][hr * 2 + 0];
                    float v1 = acc[m][n][hr * 2 + 1];
                    if (bias) { v0 += bias[col]; v1 += bias[col + 1]; }
                    const int off = (col >> 2) * 8 + (col & 3) + (is_msg ? 4 : 0);
                    *(__half2*)(dst + off) = __floats2half2_rn(v0, v1);
                }
            }
        }
    }
}

// ---------------------------------------------------------------------------
// CSR row pointers from sorted self_fea_idx
// ---------------------------------------------------------------------------
__global__ void rowptr_kernel(const int* __restrict__ self_idx)
{
    const int e = blockIdx.x * blockDim.x + threadIdx.x;
    if (e >= M_EDGES) return;
    const int s = self_idx[e];
    const int prev = (e == 0) ? -1 : self_idx[e - 1];
    for (int n = prev + 1; n <= s; n++) g_rowptr[n] = e;
    if (e == M_EDGES - 1)
        for (int n = s + 1; n <= N_NODES; n++) g_rowptr[n] = M_EDGES;
}

// ---------------------------------------------------------------------------
// K2: fused softmax + weighted hidden accumulation.
// One warp per NODE, 3 heads fused; edge loop UNROLLED BY 2 with all 6 gathers
// (+2 idx +2 weight) issued before any use -> MLP=6 per warp. (R4's failure was
// a serialized 1-deep prefetch chain; this is batched-independent issue.)
// ---------------------------------------------------------------------------
__global__ void __launch_bounds__(128, 5)
edge_kernel(const int* __restrict__ nbr_idx,
            const float* __restrict__ elem_weights,
            const float* __restrict__ gate_w2,
            const float* __restrict__ gate_b2)
{
    const int n = blockIdx.x * 4 + (threadIdx.x >> 5);
    const int lane = threadIdx.x & 31;
    if (n >= N_NODES) return;

    // Self chunks + w2 + b2 per head
    float sg[3][4], sm[3][4], w2v[3][4], b2[3];
    #pragma unroll
    for (int h = 0; h < 3; h++) {
        const uint4 u = *(const uint4*)(g_self_h + ((size_t)n * 3 + h) * 256 + lane * 8);
        const float2 a0 = __half22float2(*(__half2*)&u.x);
        const float2 a1 = __half22float2(*(__half2*)&u.y);
        const float2 a2 = __half22float2(*(__half2*)&u.z);
        const float2 a3 = __half22float2(*(__half2*)&u.w);
        sg[h][0] = a0.x; sg[h][1] = a0.y; sg[h][2] = a1.x; sg[h][3] = a1.y;
        sm[h][0] = a2.x; sm[h][1] = a2.y; sm[h][2] = a3.x; sm[h][3] = a3.y;
        const float4 wv = *(const float4*)(gate_w2 + h * 128 + lane * 4);
        w2v[h][0] = wv.x; w2v[h][1] = wv.y; w2v[h][2] = wv.z; w2v[h][3] = wv.w;
        b2[h] = gate_b2[h];
    }

    const int e0 = g_rowptr[n];
    const int e1 = g_rowptr[n + 1];

    float acc[3][4];
    float denom[3] = {0.f, 0.f, 0.f};
    #pragma unroll
    for (int h = 0; h < 3; h++)
        #pragma unroll
        for (int d = 0; d < 4; d++) acc[h][d] = 0.f;

    int e = e0;
    for (; e + 1 < e1; e += 2) {
        // batched independent loads: 2 idx, 2 weights, 6 table gathers
        const int j0 = __ldg(&nbr_idx[e]);
        const int j1 = __ldg(&nbr_idx[e + 1]);
        const float w0 = __ldg(&elem_weights[j0]);
        const float w1 = __ldg(&elem_weights[j1]);
        uint4 u0[3], u1[3];
        #pragma unroll
        for (int h = 0; h < 3; h++) {
            u0[h] = *(const uint4*)(g_nbr_h + ((size_t)j0 * 3 + h) * 256 + lane * 8);
            u1[h] = *(const uint4*)(g_nbr_h + ((size_t)j1 * 3 + h) * 256 + lane * 8);
        }

        float p0[3], p1[3], m0[3][4], m1[3][4];
        #pragma unroll
        for (int h = 0; h < 3; h++) {
            {
                const float2 a0 = __half22float2(*(__half2*)&u0[h].x);
                const float2 a1 = __half22float2(*(__half2*)&u0[h].y);
                const float2 a2 = __half22float2(*(__half2*)&u0[h].z);
                const float2 a3 = __half22float2(*(__half2*)&u0[h].w);
                p0[h] = lk(sg[h][0] + a0.x) * w2v[h][0]
                      + lk(sg[h][1] + a0.y) * w2v[h][1]
                      + lk(sg[h][2] + a1.x) * w2v[h][2]
                      + lk(sg[h][3] + a1.y) * w2v[h][3];
                m0[h][0] = a2.x; m0[h][1] = a2.y; m0[h][2] = a3.x; m0[h][3] = a3.y;
            }
            {
                const float2 a0 = __half22float2(*(__half2*)&u1[h].x);
                const float2 a1 = __half22float2(*(__half2*)&u1[h].y);
                const float2 a2 = __half22float2(*(__half2*)&u1[h].z);
                const float2 a3 = __half22float2(*(__half2*)&u1[h].w);
                p1[h] = lk(sg[h][0] + a0.x) * w2v[h][0]
                      + lk(sg[h][1] + a0.y) * w2v[h][1]
                      + lk(sg[h][2] + a1.x) * w2v[h][2]
                      + lk(sg[h][3] + a1.y) * w2v[h][3];
                m1[h][0] = a2.x; m1[h][1] = a2.y; m1[h][2] = a3.x; m1[h][3] = a3.y;
            }
        }
        // 6 interleaved butterflies
        #pragma unroll
        for (int s = 16; s >= 1; s >>= 1) {
            p0[0] += __shfl_xor_sync(0xffffffffu, p0[0], s);
            p0[1] += __shfl_xor_sync(0xffffffffu, p0[1], s);
            p0[2] += __shfl_xor_sync(0xffffffffu, p0[2], s);
            p1[0] += __shfl_xor_sync(0xffffffffu, p1[0], s);
            p1[1] += __shfl_xor_sync(0xffffffffu, p1[1], s);
            p1[2] += __shfl_xor_sync(0xffffffffu, p1[2], s);
        }
        #pragma unroll
        for (int h = 0; h < 3; h++) {
            const float ev0 = w0 * __expf(p0[h] + b2[h]);
            const float ev1 = w1 * __expf(p1[h] + b2[h]);
            denom[h] += ev0 + ev1;
            acc[h][0] += ev0 * lk(sm[h][0] + m0[h][0]) + ev1 * lk(sm[h][0] + m1[h][0]);
            acc[h][1] += ev0 * lk(sm[h][1] + m0[h][1]) + ev1 * lk(sm[h][1] + m1[h][1]);
            acc[h][2] += ev0 * lk(sm[h][2] + m0[h][2]) + ev1 * lk(sm[h][2] + m1[h][2]);
            acc[h][3] += ev0 * lk(sm[h][3] + m0[h][3]) + ev1 * lk(sm[h][3] + m1[h][3]);
        }
    }
    // tail edge
    if (e < e1) {
        const int j = __ldg(&nbr_idx[e]);
        const float w = __ldg(&elem_weights[j]);
        uint4 u[3];
        #pragma unroll
        for (int h = 0; h < 3; h++)
            u[h] = *(const uint4*)(g_nbr_h + ((size_t)j * 3 + h) * 256 + lane * 8);
        float p[3], nm[3][4];
        #pragma unroll
        for (int h = 0; h < 3; h++) {
            const float2 a0 = __half22float2(*(__half2*)&u[h].x);
            const float2 a1 = __half22float2(*(__half2*)&u[h].y);
            const float2 a2 = __half22float2(*(__half2*)&u[h].z);
            const float2 a3 = __half22float2(*(__half2*)&u[h].w);
            p[h] = lk(sg[h][0] + a0.x) * w2v[h][0]
                 + lk(sg[h][1] + a0.y) * w2v[h][1]
                 + lk(sg[h][2] + a1.x) * w2v[h][2]
                 + lk(sg[h][3] + a1.y) * w2v[h][3];
            nm[h][0] = a2.x; nm[h][1] = a2.y; nm[h][2] = a3.x; nm[h][3] = a3.y;
        }
        #pragma unroll
        for (int s = 16; s >= 1; s >>= 1) {
            p[0] += __shfl_xor_sync(0xffffffffu, p[0], s);
            p[1] += __shfl_xor_sync(0xffffffffu, p[1], s);
            p[2] += __shfl_xor_sync(0xffffffffu, p[2], s);
        }
        #pragma unroll
        for (int h = 0; h < 3; h++) {
            const float ev = w * __expf(p[h] + b2[h]);
            denom[h] += ev;
            acc[h][0] += ev * lk(sm[h][0] + nm[h][0]);
            acc[h][1] += ev * lk(sm[h][1] + nm[h][1]);
            acc[h][2] += ev * lk(sm[h][2] + nm[h][2]);
            acc[h][3] += ev * lk(sm[h][3] + nm[h][3]);
        }
    }

    #pragma unroll
    for (int h = 0; h < 3; h++) {
        const float inv = 1.f / (denom[h] + 1e-10f);
        __half2 h0 = __floats2half2_rn(acc[h][0] * inv, acc[h][1] * inv);
        __half2 h1 = __floats2half2_rn(acc[h][2] * inv, acc[h][3] * inv);
        uint2 uo;
        uo.x = *(uint32_t*)&h0;
        uo.y = *(uint32_t*)&h1;
        *(uint2*)(g_acc_h + ((size_t)h * N_NODES + n) * 128 + lane * 4) = uo;
        if (lane == 0) g_sattn[(size_t)h * N_NODES + n] = denom[h] * inv;
    }
}

// ---------------------------------------------------------------------------
// K3: out[n][f] = x[n][f] + (1/3) * sum_h ( acc[h][n] @ msg_w2[h] + sattn[h][n]*msg_b2[h][f] )
// GEMM via fp16 mma.m16n8k16: C[N x 64] = A[N x 384] @ W[384 x 64]
// ---------------------------------------------------------------------------
__global__ void __launch_bounds__(256, 2)
out_gemm_kernel(const float* __restrict__ msg_w2,
                const float* __restrict__ msg_b2,
                const float* __restrict__ X,
                float* __restrict__ out)
{
    __shared__ __half As[128][88];   // 128 nodes x 64 k (fp16)
    __shared__ __half Bst[64][88];   // 64 cols x 64 k (transposed, fp16)

    const int tid  = threadIdx.x;    // 256 threads, 8 warps
    const int wid  = tid >> 5;
    const int lane = tid & 31;
    const int gid  = lane >> 2;      // 0..7
    const int tig  = lane & 3;       // 0..3
    const int warp_m = wid & 3;      // 4 warps over 128 rows (32 each)
    const int warp_n = wid >> 2;     // 2 warps over 64 cols (32 each)
    const int n0 = blockIdx.x * 128;
    const int cb = warp_n * 32;

    float acc[2][4][4];
    #pragma unroll
    for (int mt = 0; mt < 2; mt++)
        #pragma unroll
        for (int nt = 0; nt < 4; nt++)
            #pragma unroll
            for (int jj = 0; jj < 4; jj++) acc[mt][nt][jj] = 0.f;

    #pragma unroll
    for (int kc = 0; kc < 6; kc++) {
        const int h = kc >> 1;
        const __half* asrc = g_acc_h + ((size_t)h * N_NODES + n0) * 128 + (kc & 1) * 64;
        #pragma unroll
        for (int it = 0; it < 4; it++) {
            const int f4 = tid + it * 256;
            const int node = f4 >> 3;
            const int c8 = (f4 & 7) * 8;
            *(uint4*)&As[node][c8] = *(const uint4*)(asrc + (size_t)node * 128 + c8);
        }
        const float* bsrc = msg_w2 + ((size_t)h * 128 + (kc & 1) * 64) * 64;
        #pragma unroll
        for (int i = 0; i < 16; i++) {
            const int idx = i * 256 + tid;
            const int nn = idx & 63;
            const int kk = idx >> 6;
            Bst[nn][kk] = __float2half(bsrc[(size_t)kk * 64 + nn]);
        }
        __syncthreads();

        #pragma unroll
        for (int ks = 0; ks < 4; ks++) {
            const int k0 = ks * 16;
            uint32_t a[2][4];
            #pragma unroll
            for (int mt = 0; mt < 2; mt++) {
                const int rb = warp_m * 32 + mt * 16;
                a[mt][0] = *(const uint32_t*)&As[rb + gid    ][k0 + tig * 2];
                a[mt][1] = *(const uint32_t*)&As[rb + gid + 8][k0 + tig * 2];
                a[mt][2] = *(const uint32_t*)&As[rb + gid    ][k0 + 8 + tig * 2];
                a[mt][3] = *(const uint32_t*)&As[rb + gid + 8][k0 + 8 + tig * 2];
            }
            uint32_t b[4][2];
            #pragma unroll
            for (int nt = 0; nt < 4; nt++) {
                const int col = cb + nt * 8 + gid;
                b[nt][0] = *(const uint32_t*)&Bst[col][k0 + tig * 2];
                b[nt][1] = *(const uint32_t*)&Bst[col][k0 + 8 + tig * 2];
            }
            #pragma unroll
            for (int mt = 0; mt < 2; mt++)
                #pragma unroll
                for (int nt = 0; nt < 4; nt++)
                    mma_f16(acc[mt][nt], a[mt], b[nt]);
        }
        __syncthreads();
    }

    // Epilogue
    const float inv3 = 1.f / 3.f;
    #pragma unroll
    for (int mt = 0; mt < 2; mt++) {
        #pragma unroll
        for (int hf = 0; hf < 2; hf++) {
            const int r = n0 + warp_m * 32 + mt * 16 + gid + hf * 8;
            const float s0 = g_sattn[r];
            const float s1 = g_sattn[(size_t)N_NODES + r];
            const float s2 = g_sattn[(size_t)2 * N_NODES + r];
            #pragma unroll
            for (int nt = 0; nt < 4; nt++) {
                const int c = cb + nt * 8 + tig * 2;
                const float bt0 = s0 * msg_b2[c]     + s1 * msg_b2[64 + c]     + s2 * msg_b2[128 + c];
                const float bt1 = s0 * msg_b2[c + 1] + s1 * msg_b2[64 + c + 1] + s2 * msg_b2[128 + c + 1];
                const float2 xv = *(const float2*)(X + (size_t)r * 64 + c);
                float2 o;
                o.x = inv3 * (acc[mt][nt][hf * 2 + 0] + bt0) + xv.x;
                o.y = inv3 * (acc[mt][nt][hf * 2 + 1] + bt1) + xv.y;
                *(float2*)(out + (size_t)r * 64 + c) = o;
            }
        }
    }
}

// ---------------------------------------------------------------------------
extern "C" void kernel_launch(void* const* d_in, const int* in_sizes, int n_in,
                              void* d_out, int out_size)
{
    const float* elem_weights = (const float*)d_in[0];
    const float* x            = (const float*)d_in[1];
    const int*   self_idx     = (const int*)  d_in[2];
    const int*   nbr_idx      = (const int*)  d_in[3];
    const float* gate_w1      = (const float*)d_in[4];
    const float* gate_b1      = (const float*)d_in[5];
    const float* gate_w2      = (const float*)d_in[6];
    const float* gate_b2      = (const float*)d_in[7];
    const float* msg_w1       = (const float*)d_in[8];
    const float* msg_b1       = (const float*)d_in[9];
    const float* msg_w2       = (const float*)d_in[10];
    const float* msg_b2       = (const float*)d_in[11];
    float* out = (float*)d_out;

    prep_weights_kernel<<<12, 256>>>(gate_w1, msg_w1);
    node_gemm_kernel<<<N_NODES / 128, 256>>>(x, gate_b1, msg_b1);
    rowptr_kernel<<<M_EDGES / 256, 256>>>(self_idx);
    edge_kernel<<<N_NODES / 4, 128>>>(nbr_idx, elem_weights, gate_w2, gate_b2);
    out_gemm_kernel<<<N_NODES / 128, 256>>>(msg_w2, msg_b2, x, out);
}